// round 12
// baseline (speedup 1.0000x reference)
#include <cuda_runtime.h>
#include <cuda_fp16.h>

// DifferentiableJPEG on GB300:
//   x[32,512,512,3] fp32 -> y[32,512,512,3], Xq[32*3*4096,8,8]
// d_out = [ y | Xq ] fp32.
//
// r7 structure + packed-constant hoisting: f32x2 ops cannot take immediates,
// so all packed constants (7 positive DCT coeffs, 5 series coeffs, -1) are
// hoisted ONCE into registers and threaded through the packed helpers;
// launch_bounds(256,3) gives ptxas the registers to keep them (at the 64-reg
// cap it rematerialized 2xMOV pairs per use). DCT formulas regrouped to use
// only positive constants.

typedef unsigned long long u64;

static __device__ __forceinline__ u64 pk2(float lo, float hi) {
    u64 r; asm("mov.b64 %0, {%1, %2};" : "=l"(r) : "f"(lo), "f"(hi)); return r;
}
static __device__ __forceinline__ void up2(u64 v, float& lo, float& hi) {
    asm("mov.b64 {%0, %1}, %2;" : "=f"(lo), "=f"(hi) : "l"(v));
}
static __device__ __forceinline__ u64 bc2(float c) {
    u64 r; asm("mov.b64 %0, {%1, %1};" : "=l"(r) : "f"(c)); return r;
}
static __device__ __forceinline__ u64 f2add(u64 a, u64 b) {
    u64 d; asm("add.rn.f32x2 %0, %1, %2;" : "=l"(d) : "l"(a), "l"(b)); return d;
}
static __device__ __forceinline__ u64 f2mul(u64 a, u64 b) {
    u64 d; asm("mul.rn.f32x2 %0, %1, %2;" : "=l"(d) : "l"(a), "l"(b)); return d;
}
static __device__ __forceinline__ u64 f2fma(u64 a, u64 b, u64 c) {
    u64 d; asm("fma.rn.f32x2 %0, %1, %2, %3;" : "=l"(d) : "l"(a), "l"(b), "l"(c)); return d;
}
#define F2SUB(a, b) f2fma((b), N1, (a))

// Hoisted packed constants, built once per thread.
struct PC {
    u64 N1;                                       // (-1,-1)
    u64 c3536, c4619, c1913, c4904, c4157, c2778, c0975;
    u64 k1, k2, k3, k4, k5;                       // signed series coeffs
};

static __device__ __forceinline__ float round_sin5(float u) {
    float r  = u - rintf(u);
    float a  = 6.283185307179586f * r;
    float s1, c1;
    __sincosf(a, &s1, &c1);
    float tc = 2.0f * c1;
    float s2 = tc * s1;
    float s3 = fmaf(tc, s2, -s1);
    float s4 = fmaf(tc, s3, -s2);
    float s5 = fmaf(tc, s4, -s3);
    float S  = 0.3183098861837907f  * s1
             - 0.15915494309189535f * s2
             + 0.10610329539459689f * s3
             - 0.07957747154594767f * s4
             + 0.06366197723675814f * s5;
    return u - S;
}

static __device__ __forceinline__ u64 round_sin5_2(u64 u, const PC& pc) {
    const u64 N1 = pc.N1;
    float ul, uh; up2(u, ul, uh);
    float rl = ul - rintf(ul), rh = uh - rintf(uh);
    float al = 6.283185307179586f * rl;
    float ah = 6.283185307179586f * rh;
    float sl, cl, sh, ch;
    __sincosf(al, &sl, &cl);
    __sincosf(ah, &sh, &ch);
    u64 s1 = pk2(sl, sh);
    u64 tc = pk2(cl + cl, ch + ch);
    u64 s2 = f2mul(tc, s1);
    u64 s3 = f2fma(tc, s2, f2mul(s1, N1));
    u64 s4 = f2fma(tc, s3, f2mul(s2, N1));
    u64 s5 = f2fma(tc, s4, f2mul(s3, N1));
    u64 S  = f2mul(pc.k1, s1);
    S = f2fma(pc.k2, s2, S);
    S = f2fma(pc.k3, s3, S);
    S = f2fma(pc.k4, s4, S);
    S = f2fma(pc.k5, s5, S);
    return f2fma(S, N1, u);
}

// scalar even/odd DCT (constants are FFMA immediates -- free)
static __device__ __forceinline__ void fdct8(const float a[8], float o[8]) {
    float e0 = a[0] + a[7], e1 = a[1] + a[6], e2 = a[2] + a[5], e3 = a[3] + a[4];
    float d0 = a[0] - a[7], d1 = a[1] - a[6], d2 = a[2] - a[5], d3 = a[3] - a[4];
    float g0 = e0 + e3, g1 = e1 + e2, g2 = e0 - e3, g3 = e1 - e2;
    o[0] = 0.3536f * (g0 + g1);
    o[4] = 0.3536f * (g0 - g1);
    o[2] = fmaf( 0.4619f, g2,  0.1913f * g3);
    o[6] = fmaf(-0.4619f, g3,  0.1913f * g2);
    o[1] = fmaf(0.4904f, d0, fmaf( 0.4157f, d1, fmaf( 0.2778f, d2,  0.0975f * d3)));
    o[3] = fmaf(0.4157f, d0, fmaf(-0.0975f, d1, fmaf(-0.4904f, d2, -0.2778f * d3)));
    o[5] = fmaf(0.2778f, d0, fmaf(-0.4904f, d1, fmaf( 0.0975f, d2,  0.4157f * d3)));
    o[7] = fmaf(0.0975f, d0, fmaf(-0.2778f, d1, fmaf( 0.4157f, d2, -0.4904f * d3)));
}

static __device__ __forceinline__ void idct8(const float a[8], float o[8]) {
    float t0 = 0.3536f * (a[0] + a[4]);
    float t1 = 0.3536f * (a[0] - a[4]);
    float u0 = fmaf(0.4619f, a[2],  0.1913f * a[6]);
    float u1 = fmaf(0.1913f, a[2], -0.4619f * a[6]);
    float E0 = t0 + u0, E1 = t1 + u1, E2 = t1 - u1, E3 = t0 - u0;
    float D0 = fmaf(0.4904f, a[1], fmaf( 0.4157f, a[3], fmaf( 0.2778f, a[5],  0.0975f * a[7])));
    float D1 = fmaf(0.4157f, a[1], fmaf(-0.0975f, a[3], fmaf(-0.4904f, a[5], -0.2778f * a[7])));
    float D2 = fmaf(0.2778f, a[1], fmaf(-0.4904f, a[3], fmaf( 0.0975f, a[5],  0.4157f * a[7])));
    float D3 = fmaf(0.0975f, a[1], fmaf(-0.2778f, a[3], fmaf( 0.4157f, a[5], -0.4904f * a[7])));
    o[0] = E0 + D0;  o[7] = E0 - D0;
    o[1] = E1 + D1;  o[6] = E1 - D1;
    o[2] = E2 + D2;  o[5] = E2 - D2;
    o[3] = E3 + D3;  o[4] = E3 - D3;
}

// packed, positive-constants-only versions
static __device__ __forceinline__ void fdct8_2(const u64 a[8], u64 o[8], const PC& pc) {
    const u64 N1 = pc.N1;
    u64 e0 = f2add(a[0], a[7]), e1 = f2add(a[1], a[6]);
    u64 e2 = f2add(a[2], a[5]), e3 = f2add(a[3], a[4]);
    u64 d0 = F2SUB(a[0], a[7]), d1 = F2SUB(a[1], a[6]);
    u64 d2 = F2SUB(a[2], a[5]), d3 = F2SUB(a[3], a[4]);
    u64 g0 = f2add(e0, e3), g1 = f2add(e1, e2);
    u64 g2 = F2SUB(e0, e3), g3 = F2SUB(e1, e2);
    o[0] = f2mul(pc.c3536, f2add(g0, g1));
    o[4] = f2mul(pc.c3536, F2SUB(g0, g1));
    o[2] = f2fma(pc.c4619, g2, f2mul(pc.c1913, g3));
    o[6] = F2SUB(f2mul(pc.c1913, g2), f2mul(pc.c4619, g3));
    o[1] = f2fma(pc.c4904, d0, f2fma(pc.c4157, d1, f2fma(pc.c2778, d2, f2mul(pc.c0975, d3))));
    // 0.4157 d0 - (0.0975 d1 + 0.4904 d2 + 0.2778 d3)
    o[3] = F2SUB(f2mul(pc.c4157, d0), f2fma(pc.c0975, d1, f2fma(pc.c4904, d2, f2mul(pc.c2778, d3))));
    // (0.2778 d0 + 0.0975 d2 + 0.4157 d3) - 0.4904 d1
    o[5] = F2SUB(f2fma(pc.c2778, d0, f2fma(pc.c0975, d2, f2mul(pc.c4157, d3))), f2mul(pc.c4904, d1));
    // (0.0975 d0 + 0.4157 d2) - (0.2778 d1 + 0.4904 d3)
    o[7] = F2SUB(f2fma(pc.c0975, d0, f2mul(pc.c4157, d2)), f2fma(pc.c2778, d1, f2mul(pc.c4904, d3)));
}

static __device__ __forceinline__ void idct8_2(const u64 a[8], u64 o[8], const PC& pc) {
    const u64 N1 = pc.N1;
    u64 t0 = f2mul(pc.c3536, f2add(a[0], a[4]));
    u64 t1 = f2mul(pc.c3536, F2SUB(a[0], a[4]));
    u64 u0 = f2fma(pc.c4619, a[2], f2mul(pc.c1913, a[6]));
    u64 u1 = F2SUB(f2mul(pc.c1913, a[2]), f2mul(pc.c4619, a[6]));
    u64 E0 = f2add(t0, u0), E1 = f2add(t1, u1);
    u64 E2 = F2SUB(t1, u1), E3 = F2SUB(t0, u0);
    u64 D0 = f2fma(pc.c4904, a[1], f2fma(pc.c4157, a[3], f2fma(pc.c2778, a[5], f2mul(pc.c0975, a[7]))));
    u64 D1 = F2SUB(f2mul(pc.c4157, a[1]), f2fma(pc.c0975, a[3], f2fma(pc.c4904, a[5], f2mul(pc.c2778, a[7]))));
    u64 D2 = F2SUB(f2fma(pc.c2778, a[1], f2fma(pc.c0975, a[5], f2mul(pc.c4157, a[7]))), f2mul(pc.c4904, a[3]));
    u64 D3 = F2SUB(f2fma(pc.c0975, a[1], f2mul(pc.c4157, a[5])), f2fma(pc.c2778, a[3], f2mul(pc.c4904, a[7])));
    o[0] = f2add(E0, D0);  o[7] = F2SUB(E0, D0);
    o[1] = f2add(E1, D1);  o[6] = F2SUB(E1, D1);
    o[2] = f2add(E2, D2);  o[5] = F2SUB(E2, D2);
    o[3] = f2add(E3, D3);  o[4] = F2SUB(E3, D3);
}

// float (Y) transpose: row stride 12 floats, tile stride 104 (conflict-free)
#define TROW 12
#define TTILE 104
// u64 (CbCr): row stride 10 u64 (STS.128 quad-phases CF), tile stride 88
// (= 8 mod 16 -> u64 column-read half-phases CF)
#define UROW 10
#define UTILE 88

__global__ __launch_bounds__(256, 3)
void jpeg_kernel(const float* __restrict__ x,
                 const float* __restrict__ q_luma,
                 const float* __restrict__ q_chroma,
                 float* __restrict__ y_out,
                 float* __restrict__ xq_out)
{
    __shared__ __align__(16) float tf[32 * TTILE];  // 13.3 KB, Y transposes
    __shared__ __align__(16) u64   tu[32 * UTILE];  // 22.5 KB, CbCr transposes

    PC pc;
    pc.N1    = bc2(-1.0f);
    pc.c3536 = bc2(0.3536f);
    pc.c4619 = bc2(0.4619f);
    pc.c1913 = bc2(0.1913f);
    pc.c4904 = bc2(0.4904f);
    pc.c4157 = bc2(0.4157f);
    pc.c2778 = bc2(0.2778f);
    pc.c0975 = bc2(0.0975f);
    pc.k1 = bc2( 0.3183098861837907f);
    pc.k2 = bc2(-0.15915494309189535f);
    pc.k3 = bc2( 0.10610329539459689f);
    pc.k4 = bc2(-0.07957747154594767f);
    pc.k5 = bc2( 0.06366197723675814f);

    const int t  = threadIdx.x >> 3;
    const int r  = threadIdx.x & 7;
    const int tg = blockIdx.x * 32 + t;
    const int b   = tg >> 12;
    const int rem = tg & 4095;
    const int bh  = rem >> 6;
    const int bw  = rem & 63;

    float* sf = tf + t * TTILE;
    u64*   su = tu + t * UTILE;

    // Q columns (column r), packed half2 (exact: integers <= 255)
    __half2 qh[2][4];
#pragma unroll
    for (int j = 0; j < 4; j++) {
        qh[0][j] = __floats2half2_rn(q_luma  [(2*j  ) * 8 + r], q_luma  [(2*j+1) * 8 + r]);
        qh[1][j] = __floats2half2_rn(q_chroma[(2*j  ) * 8 + r], q_chroma[(2*j+1) * 8 + r]);
    }

    // load this row: 8 pixels x RGB = 24 contiguous floats
    const int pix_off = (((b * 512 + bh * 8 + r) * 512) + bw * 8) * 3;
    float px[24];
    {
        const float4* xin4 = (const float4*)(x + pix_off);
#pragma unroll
        for (int v = 0; v < 6; v++) {
            float4 q4 = xin4[v];
            px[v*4+0] = q4.x; px[v*4+1] = q4.y; px[v*4+2] = q4.z; px[v*4+3] = q4.w;
        }
    }

    // RGB -> YCbCr - 127; Y scalar, Cb/Cr packed
    float yy[8];
    u64 P[8];
#pragma unroll
    for (int p = 0; p < 8; p++) {
        float R = 255.0f * px[3*p+0];
        float G = 255.0f * px[3*p+1];
        float Bv= 255.0f * px[3*p+2];
        yy[p] = fmaf(0.299f, R, fmaf(0.587f, G, 0.114f * Bv)) - 127.0f;
        float cb = fmaf(-0.168736f, R, fmaf(-0.331264f, G,  0.5f      * Bv)) + 1.0f;
        float cr = fmaf(0.5f,       R, fmaf(-0.418688f, G, -0.081312f * Bv)) + 1.0f;
        P[p] = pk2(cb, cr);
    }

    const size_t blk64 = ((size_t)(b * 3 * 4096 + bh * 64 + bw)) << 6;

    // ======== Y channel (scalar) ========
    {
        float a[8], o[8];
#pragma unroll
        for (int j = 0; j < 8; j++) a[j] = yy[j];
        fdct8(a, o);

        {   // transpose 1
            float4* sp = (float4*)(sf + r * TROW);
            sp[0] = make_float4(o[0], o[1], o[2], o[3]);
            sp[1] = make_float4(o[4], o[5], o[6], o[7]);
        }
        __syncwarp();
#pragma unroll
        for (int j = 0; j < 8; j++) a[j] = sf[j * TROW + r];
        __syncwarp();

        fdct8(a, o);

#pragma unroll
        for (int j = 0; j < 8; j++) {
            __half2 h2 = qh[0][j >> 1];
            float qf = (j & 1) ? __high2float(h2) : __low2float(h2);
            float u  = __fdividef(o[j], qf);
            a[j] = round_sin5(u) * qf;
        }
        {
            float* xqp = xq_out + blk64 + r;
#pragma unroll
            for (int j = 0; j < 8; j++) xqp[j * 8] = a[j];
        }

        idct8(a, o);
        {   // transpose 2
            float4* sp = (float4*)(sf + r * TROW);
            sp[0] = make_float4(o[0], o[1], o[2], o[3]);
            sp[1] = make_float4(o[4], o[5], o[6], o[7]);
        }
        __syncwarp();
#pragma unroll
        for (int j = 0; j < 8; j++) a[j] = sf[j * TROW + r];

        idct8(a, yy);           // yy now holds ib_Y row r
    }

    // ======== Cb/Cr pair (packed f32x2) ========
    u64 A[8], O[8];
#pragma unroll
    for (int j = 0; j < 8; j++) A[j] = P[j];
    fdct8_2(A, O, pc);

    {   // transpose 1: vectorized row store (4x STS.128)
        ulonglong2* sp = (ulonglong2*)(su + r * UROW);
        sp[0] = make_ulonglong2(O[0], O[1]);
        sp[1] = make_ulonglong2(O[2], O[3]);
        sp[2] = make_ulonglong2(O[4], O[5]);
        sp[3] = make_ulonglong2(O[6], O[7]);
    }
    __syncwarp();
#pragma unroll
    for (int j = 0; j < 8; j++) A[j] = su[j * UROW + r];
    __syncwarp();

    fdct8_2(A, O, pc);

#pragma unroll
    for (int j = 0; j < 8; j++) {
        __half2 h2 = qh[1][j >> 1];
        float qf = (j & 1) ? __high2float(h2) : __low2float(h2);
        float rq = __fdividef(1.0f, qf);
        u64 u = f2mul(O[j], bc2(rq));
        A[j] = f2mul(round_sin5_2(u, pc), bc2(qf));
    }
    {
        float* xq1 = xq_out + blk64 + (size_t)(4096 * 64)     + r;
        float* xq2 = xq_out + blk64 + (size_t)(2 * 4096 * 64) + r;
#pragma unroll
        for (int j = 0; j < 8; j++) {
            float cb, cr; up2(A[j], cb, cr);
            xq1[j * 8] = cb;
            xq2[j * 8] = cr;
        }
    }

    idct8_2(A, O, pc);

    {   // transpose 2
        ulonglong2* sp = (ulonglong2*)(su + r * UROW);
        sp[0] = make_ulonglong2(O[0], O[1]);
        sp[1] = make_ulonglong2(O[2], O[3]);
        sp[2] = make_ulonglong2(O[4], O[5]);
        sp[3] = make_ulonglong2(O[6], O[7]);
    }
    __syncwarp();
#pragma unroll
    for (int j = 0; j < 8; j++) A[j] = su[j * UROW + r];

    idct8_2(A, O, pc);          // O[p] = packed (ib_Cb, ib_Cr) for pixel p

    // YCbCr -> RGB, /255, clip
#pragma unroll
    for (int p = 0; p < 8; p++) {
        float cbv, crv; up2(O[p], cbv, crv);
        float Y  = yy[p] + 127.0f;
        float Cb = cbv  + 127.0f;
        float Cr = crv  + 127.0f;
        float R = fmaf(1.402f,  Cr, Y) + (-1.402f  * 128.0f);
        float G = fmaf(-0.344136f, Cb, fmaf(-0.714136f, Cr, Y)) + (1.058272f * 128.0f);
        float Bv= fmaf(1.772f,  Cb, Y) + (-1.772f  * 128.0f);
        px[3*p+0] = fminf(fmaxf(R  * (1.0f/255.0f), 0.0f), 1.0f);
        px[3*p+1] = fminf(fmaxf(G  * (1.0f/255.0f), 0.0f), 1.0f);
        px[3*p+2] = fminf(fmaxf(Bv * (1.0f/255.0f), 0.0f), 1.0f);
    }
    {
        float4* yo4 = (float4*)(y_out + pix_off);
#pragma unroll
        for (int v = 0; v < 6; v++) {
            float4 q4;
            q4.x = px[v*4+0]; q4.y = px[v*4+1]; q4.z = px[v*4+2]; q4.w = px[v*4+3];
            yo4[v] = q4;
        }
    }
}

extern "C" void kernel_launch(void* const* d_in, const int* in_sizes, int n_in,
                              void* d_out, int out_size)
{
    const float* x  = (const float*)d_in[0];
    const float* ql = (const float*)d_in[1];
    const float* qc = (const float*)d_in[2];

    float* y  = (float*)d_out;
    float* xq = (float*)d_out + (size_t)32 * 512 * 512 * 3;

    jpeg_kernel<<<4096, 256>>>(x, ql, qc, y, xq);
}

// round 13
// speedup vs baseline: 1.2740x; 1.2740x over previous
#include <cuda_runtime.h>
#include <cuda_fp16.h>

// DifferentiableJPEG on GB300:
//   x[32,512,512,3] fp32 -> y[32,512,512,3], Xq[32*3*4096,8,8]
// d_out = [ y | Xq ] fp32.
//
// KEY CHANGE (r13): x loads / y stores were the hidden L1TEX killer -- the
// 8 rows of a warp are 6KB apart, so each "vectorized" LDG.128/STG.128
// warp instruction touched ~20+ cache lines (~240 wavefronts/warp total).
// Now the CTA's 8x256px RGB region (24KB) is staged through shared memory
// with fully coalesced cooperative LDG/STG.128 (4 wavefronts/instr), and
// threads read/write their rows from smem (pad-772 row stride ->
// conflict-free LDS/STS.128). Compute pipeline = r7: Y scalar, Cb/Cr packed
// f32x2, warp-local transposes in per-warp private slices of the SAME
// buffer (no cross-warp aliasing).

typedef unsigned long long u64;

static __device__ __forceinline__ u64 pk2(float lo, float hi) {
    u64 r; asm("mov.b64 %0, {%1, %2};" : "=l"(r) : "f"(lo), "f"(hi)); return r;
}
static __device__ __forceinline__ void up2(u64 v, float& lo, float& hi) {
    asm("mov.b64 {%0, %1}, %2;" : "=f"(lo), "=f"(hi) : "l"(v));
}
static __device__ __forceinline__ u64 bc2(float c) {
    u64 r; asm("mov.b64 %0, {%1, %1};" : "=l"(r) : "f"(c)); return r;
}
static __device__ __forceinline__ u64 f2add(u64 a, u64 b) {
    u64 d; asm("add.rn.f32x2 %0, %1, %2;" : "=l"(d) : "l"(a), "l"(b)); return d;
}
static __device__ __forceinline__ u64 f2mul(u64 a, u64 b) {
    u64 d; asm("mul.rn.f32x2 %0, %1, %2;" : "=l"(d) : "l"(a), "l"(b)); return d;
}
static __device__ __forceinline__ u64 f2fma(u64 a, u64 b, u64 c) {
    u64 d; asm("fma.rn.f32x2 %0, %1, %2, %3;" : "=l"(d) : "l"(a), "l"(b), "l"(c)); return d;
}
#define F2SUB(a, b) f2fma((b), N1, (a))

static __device__ __forceinline__ float round_sin5(float u) {
    float r  = u - rintf(u);
    float a  = 6.283185307179586f * r;
    float s1, c1;
    __sincosf(a, &s1, &c1);
    float tc = 2.0f * c1;
    float s2 = tc * s1;
    float s3 = fmaf(tc, s2, -s1);
    float s4 = fmaf(tc, s3, -s2);
    float s5 = fmaf(tc, s4, -s3);
    float S  = 0.3183098861837907f  * s1
             - 0.15915494309189535f * s2
             + 0.10610329539459689f * s3
             - 0.07957747154594767f * s4
             + 0.06366197723675814f * s5;
    return u - S;
}

static __device__ __forceinline__ u64 round_sin5_2(u64 u, u64 N1) {
    float ul, uh; up2(u, ul, uh);
    float rl = ul - rintf(ul), rh = uh - rintf(uh);
    float al = 6.283185307179586f * rl;
    float ah = 6.283185307179586f * rh;
    float sl, cl, sh, ch;
    __sincosf(al, &sl, &cl);
    __sincosf(ah, &sh, &ch);
    u64 s1 = pk2(sl, sh);
    u64 tc = pk2(cl + cl, ch + ch);
    u64 s2 = f2mul(tc, s1);
    u64 s3 = f2fma(tc, s2, f2mul(s1, N1));
    u64 s4 = f2fma(tc, s3, f2mul(s2, N1));
    u64 s5 = f2fma(tc, s4, f2mul(s3, N1));
    u64 S  = f2mul(bc2(0.3183098861837907f), s1);
    S = f2fma(bc2(-0.15915494309189535f), s2, S);
    S = f2fma(bc2(0.10610329539459689f),  s3, S);
    S = f2fma(bc2(-0.07957747154594767f), s4, S);
    S = f2fma(bc2(0.06366197723675814f),  s5, S);
    return f2fma(S, N1, u);
}

static __device__ __forceinline__ void fdct8(const float a[8], float o[8]) {
    float e0 = a[0] + a[7], e1 = a[1] + a[6], e2 = a[2] + a[5], e3 = a[3] + a[4];
    float d0 = a[0] - a[7], d1 = a[1] - a[6], d2 = a[2] - a[5], d3 = a[3] - a[4];
    float g0 = e0 + e3, g1 = e1 + e2, g2 = e0 - e3, g3 = e1 - e2;
    o[0] = 0.3536f * (g0 + g1);
    o[4] = 0.3536f * (g0 - g1);
    o[2] = fmaf( 0.4619f, g2,  0.1913f * g3);
    o[6] = fmaf(-0.4619f, g3,  0.1913f * g2);
    o[1] = fmaf(0.4904f, d0, fmaf( 0.4157f, d1, fmaf( 0.2778f, d2,  0.0975f * d3)));
    o[3] = fmaf(0.4157f, d0, fmaf(-0.0975f, d1, fmaf(-0.4904f, d2, -0.2778f * d3)));
    o[5] = fmaf(0.2778f, d0, fmaf(-0.4904f, d1, fmaf( 0.0975f, d2,  0.4157f * d3)));
    o[7] = fmaf(0.0975f, d0, fmaf(-0.2778f, d1, fmaf( 0.4157f, d2, -0.4904f * d3)));
}

static __device__ __forceinline__ void idct8(const float a[8], float o[8]) {
    float t0 = 0.3536f * (a[0] + a[4]);
    float t1 = 0.3536f * (a[0] - a[4]);
    float u0 = fmaf(0.4619f, a[2],  0.1913f * a[6]);
    float u1 = fmaf(0.1913f, a[2], -0.4619f * a[6]);
    float E0 = t0 + u0, E1 = t1 + u1, E2 = t1 - u1, E3 = t0 - u0;
    float D0 = fmaf(0.4904f, a[1], fmaf( 0.4157f, a[3], fmaf( 0.2778f, a[5],  0.0975f * a[7])));
    float D1 = fmaf(0.4157f, a[1], fmaf(-0.0975f, a[3], fmaf(-0.4904f, a[5], -0.2778f * a[7])));
    float D2 = fmaf(0.2778f, a[1], fmaf(-0.4904f, a[3], fmaf( 0.0975f, a[5],  0.4157f * a[7])));
    float D3 = fmaf(0.0975f, a[1], fmaf(-0.2778f, a[3], fmaf( 0.4157f, a[5], -0.4904f * a[7])));
    o[0] = E0 + D0;  o[7] = E0 - D0;
    o[1] = E1 + D1;  o[6] = E1 - D1;
    o[2] = E2 + D2;  o[5] = E2 - D2;
    o[3] = E3 + D3;  o[4] = E3 - D3;
}

static __device__ __forceinline__ void fdct8_2(const u64 a[8], u64 o[8], u64 N1) {
    u64 e0 = f2add(a[0], a[7]), e1 = f2add(a[1], a[6]);
    u64 e2 = f2add(a[2], a[5]), e3 = f2add(a[3], a[4]);
    u64 d0 = F2SUB(a[0], a[7]), d1 = F2SUB(a[1], a[6]);
    u64 d2 = F2SUB(a[2], a[5]), d3 = F2SUB(a[3], a[4]);
    u64 g0 = f2add(e0, e3), g1 = f2add(e1, e2);
    u64 g2 = F2SUB(e0, e3), g3 = F2SUB(e1, e2);
    o[0] = f2mul(bc2(0.3536f), f2add(g0, g1));
    o[4] = f2mul(bc2(0.3536f), F2SUB(g0, g1));
    o[2] = f2fma(bc2( 0.4619f), g2, f2mul(bc2(0.1913f), g3));
    o[6] = f2fma(bc2(-0.4619f), g3, f2mul(bc2(0.1913f), g2));
    o[1] = f2fma(bc2(0.4904f), d0, f2fma(bc2( 0.4157f), d1, f2fma(bc2( 0.2778f), d2, f2mul(bc2( 0.0975f), d3))));
    o[3] = f2fma(bc2(0.4157f), d0, f2fma(bc2(-0.0975f), d1, f2fma(bc2(-0.4904f), d2, f2mul(bc2(-0.2778f), d3))));
    o[5] = f2fma(bc2(0.2778f), d0, f2fma(bc2(-0.4904f), d1, f2fma(bc2( 0.0975f), d2, f2mul(bc2( 0.4157f), d3))));
    o[7] = f2fma(bc2(0.0975f), d0, f2fma(bc2(-0.2778f), d1, f2fma(bc2( 0.4157f), d2, f2mul(bc2(-0.4904f), d3))));
}

static __device__ __forceinline__ void idct8_2(const u64 a[8], u64 o[8], u64 N1) {
    u64 t0 = f2mul(bc2(0.3536f), f2add(a[0], a[4]));
    u64 t1 = f2mul(bc2(0.3536f), F2SUB(a[0], a[4]));
    u64 u0 = f2fma(bc2(0.4619f), a[2], f2mul(bc2( 0.1913f), a[6]));
    u64 u1 = f2fma(bc2(0.1913f), a[2], f2mul(bc2(-0.4619f), a[6]));
    u64 E0 = f2add(t0, u0), E1 = f2add(t1, u1);
    u64 E2 = F2SUB(t1, u1), E3 = F2SUB(t0, u0);
    u64 D0 = f2fma(bc2(0.4904f), a[1], f2fma(bc2( 0.4157f), a[3], f2fma(bc2( 0.2778f), a[5], f2mul(bc2( 0.0975f), a[7]))));
    u64 D1 = f2fma(bc2(0.4157f), a[1], f2fma(bc2(-0.0975f), a[3], f2fma(bc2(-0.4904f), a[5], f2mul(bc2(-0.2778f), a[7]))));
    u64 D2 = f2fma(bc2(0.2778f), a[1], f2fma(bc2(-0.4904f), a[3], f2fma(bc2( 0.0975f), a[5], f2mul(bc2( 0.4157f), a[7]))));
    u64 D3 = f2fma(bc2(0.0975f), a[1], f2fma(bc2(-0.2778f), a[3], f2fma(bc2( 0.4157f), a[5], f2mul(bc2(-0.4904f), a[7]))));
    o[0] = f2add(E0, D0);  o[7] = F2SUB(E0, D0);
    o[1] = f2add(E1, D1);  o[6] = F2SUB(E1, D1);
    o[2] = f2add(E2, D2);  o[5] = F2SUB(E2, D2);
    o[3] = f2add(E3, D3);  o[4] = F2SUB(E3, D3);
}

// staging: 8 image rows, 772-float stride (3088B = 16 mod 128 -> per-thread
// row accesses hit distinct 16B slots). Data = 768 floats/row.
#define SROW 772
// per-warp private scratch inside the same buffer: 704 floats (2816B, = 0
// mod 128 -> bank geometry preserved). Holds Y transposes (4 tiles x 104
// floats) then CbCr transposes (4 tiles x 88 u64) sequentially.
#define WSCR 704
#define TROW 12
#define TTILE 104
#define UROW 10
#define UTILE 88

__global__ __launch_bounds__(256, 4)
void jpeg_kernel(const float* __restrict__ x,
                 const float* __restrict__ q_luma,
                 const float* __restrict__ q_chroma,
                 float* __restrict__ y_out,
                 float* __restrict__ xq_out)
{
    __shared__ __align__(16) float stage[8 * SROW];   // 24.1 KB, multi-purpose

    const u64 N1 = bc2(-1.0f);

    const int tid = threadIdx.x;
    const int t  = tid >> 3;            // tile within CTA (0..31)
    const int r  = tid & 7;             // row within tile
    const int tg = blockIdx.x * 32 + t;
    const int tgb = blockIdx.x * 32;
    const int b   = tgb >> 12;
    const int bh  = (tgb & 4095) >> 6;
    const int bw0 = tgb & 63;           // CTA's first tile column (mult of 32)

    // per-warp private scratch views
    float* sw = stage + (tid >> 5) * WSCR;
    float* sf = sw + (t & 3) * TTILE;
    u64*   su = (u64*)sw + (t & 3) * UTILE;

    // ---- 1. cooperative coalesced load: x region -> stage ----
    // region: rows bh*8..+8, cols bw0*8..+256, all 3 channels
    const float* xbase = x + ((size_t)(b * 512 + bh * 8) * 512 + bw0 * 8) * 3;
#pragma unroll
    for (int i = 0; i < 6; i++) {
        int idx4 = tid + i * 256;           // 0..1535 float4s
        int row  = idx4 / 192;              // 192 float4 per image row
        int c4   = idx4 - row * 192;
        float4 v = *(const float4*)(xbase + row * 1536 + c4 * 4);
        *(float4*)(stage + row * SROW + c4 * 4) = v;
    }
    __syncthreads();

    // Q columns (column r), packed half2 (exact: integers <= 255)
    __half2 qh[2][4];
#pragma unroll
    for (int j = 0; j < 4; j++) {
        qh[0][j] = __floats2half2_rn(q_luma  [(2*j  ) * 8 + r], q_luma  [(2*j+1) * 8 + r]);
        qh[1][j] = __floats2half2_rn(q_chroma[(2*j  ) * 8 + r], q_chroma[(2*j+1) * 8 + r]);
    }

    // ---- 2. per-thread: read my 24 floats from stage (conflict-free) ----
    float px[24];
    {
        const float4* sp = (const float4*)(stage + r * SROW + t * 24);
#pragma unroll
        for (int v = 0; v < 6; v++) {
            float4 q4 = sp[v];
            px[v*4+0] = q4.x; px[v*4+1] = q4.y; px[v*4+2] = q4.z; px[v*4+3] = q4.w;
        }
    }
    __syncthreads();   // all inputs consumed before scratch overlays write

    // RGB -> YCbCr - 127; Y scalar, Cb/Cr packed
    float yy[8];
    u64 P[8];
#pragma unroll
    for (int p = 0; p < 8; p++) {
        float R = 255.0f * px[3*p+0];
        float G = 255.0f * px[3*p+1];
        float Bv= 255.0f * px[3*p+2];
        yy[p] = fmaf(0.299f, R, fmaf(0.587f, G, 0.114f * Bv)) - 127.0f;
        float cb = fmaf(-0.168736f, R, fmaf(-0.331264f, G,  0.5f      * Bv)) + 1.0f;
        float cr = fmaf(0.5f,       R, fmaf(-0.418688f, G, -0.081312f * Bv)) + 1.0f;
        P[p] = pk2(cb, cr);
    }

    const size_t blk64 = ((size_t)(b * 3 * 4096 + (tg & 4095))) << 6;

    // ======== Y channel (scalar), warp-local scratch ========
    {
        float a[8], o[8];
#pragma unroll
        for (int j = 0; j < 8; j++) a[j] = yy[j];
        fdct8(a, o);

        {   // transpose 1
            float4* sp = (float4*)(sf + r * TROW);
            sp[0] = make_float4(o[0], o[1], o[2], o[3]);
            sp[1] = make_float4(o[4], o[5], o[6], o[7]);
        }
        __syncwarp();
#pragma unroll
        for (int j = 0; j < 8; j++) a[j] = sf[j * TROW + r];
        __syncwarp();

        fdct8(a, o);

#pragma unroll
        for (int j = 0; j < 8; j++) {
            __half2 h2 = qh[0][j >> 1];
            float qf = (j & 1) ? __high2float(h2) : __low2float(h2);
            float u  = __fdividef(o[j], qf);
            a[j] = round_sin5(u) * qf;
        }
        {
            float* xqp = xq_out + blk64 + r;
#pragma unroll
            for (int j = 0; j < 8; j++) xqp[j * 8] = a[j];
        }

        idct8(a, o);
        {   // transpose 2
            float4* sp = (float4*)(sf + r * TROW);
            sp[0] = make_float4(o[0], o[1], o[2], o[3]);
            sp[1] = make_float4(o[4], o[5], o[6], o[7]);
        }
        __syncwarp();
#pragma unroll
        for (int j = 0; j < 8; j++) a[j] = sf[j * TROW + r];
        __syncwarp();   // done with float view before u64 view overwrites

        idct8(a, yy);   // yy now holds ib_Y row r
    }

    // ======== Cb/Cr pair (packed f32x2), warp-local scratch ========
    u64 A[8], O[8];
#pragma unroll
    for (int j = 0; j < 8; j++) A[j] = P[j];
    fdct8_2(A, O, N1);

    {   // transpose 1: vectorized row store (4x STS.128)
        ulonglong2* sp = (ulonglong2*)(su + r * UROW);
        sp[0] = make_ulonglong2(O[0], O[1]);
        sp[1] = make_ulonglong2(O[2], O[3]);
        sp[2] = make_ulonglong2(O[4], O[5]);
        sp[3] = make_ulonglong2(O[6], O[7]);
    }
    __syncwarp();
#pragma unroll
    for (int j = 0; j < 8; j++) A[j] = su[j * UROW + r];
    __syncwarp();

    fdct8_2(A, O, N1);

#pragma unroll
    for (int j = 0; j < 8; j++) {
        __half2 h2 = qh[1][j >> 1];
        float qf = (j & 1) ? __high2float(h2) : __low2float(h2);
        float rq = __fdividef(1.0f, qf);
        u64 u = f2mul(O[j], bc2(rq));
        A[j] = f2mul(round_sin5_2(u, N1), bc2(qf));
    }
    {
        float* xq1 = xq_out + blk64 + (size_t)(4096 * 64)     + r;
        float* xq2 = xq_out + blk64 + (size_t)(2 * 4096 * 64) + r;
#pragma unroll
        for (int j = 0; j < 8; j++) {
            float cb, cr; up2(A[j], cb, cr);
            xq1[j * 8] = cb;
            xq2[j * 8] = cr;
        }
    }

    idct8_2(A, O, N1);

    {   // transpose 2
        ulonglong2* sp = (ulonglong2*)(su + r * UROW);
        sp[0] = make_ulonglong2(O[0], O[1]);
        sp[1] = make_ulonglong2(O[2], O[3]);
        sp[2] = make_ulonglong2(O[4], O[5]);
        sp[3] = make_ulonglong2(O[6], O[7]);
    }
    __syncwarp();
#pragma unroll
    for (int j = 0; j < 8; j++) A[j] = su[j * UROW + r];

    idct8_2(A, O, N1);  // O[p] = packed (ib_Cb, ib_Cr) for pixel p

    // YCbCr -> RGB, /255, clip
#pragma unroll
    for (int p = 0; p < 8; p++) {
        float cbv, crv; up2(O[p], cbv, crv);
        float Y  = yy[p] + 127.0f;
        float Cb = cbv  + 127.0f;
        float Cr = crv  + 127.0f;
        float R = fmaf(1.402f,  Cr, Y) + (-1.402f  * 128.0f);
        float G = fmaf(-0.344136f, Cb, fmaf(-0.714136f, Cr, Y)) + (1.058272f * 128.0f);
        float Bv= fmaf(1.772f,  Cb, Y) + (-1.772f  * 128.0f);
        px[3*p+0] = fminf(fmaxf(R  * (1.0f/255.0f), 0.0f), 1.0f);
        px[3*p+1] = fminf(fmaxf(G  * (1.0f/255.0f), 0.0f), 1.0f);
        px[3*p+2] = fminf(fmaxf(Bv * (1.0f/255.0f), 0.0f), 1.0f);
    }

    // ---- 3. stage y rows back (all scratch use finished CTA-wide) ----
    __syncthreads();
    {
        float4* sp = (float4*)(stage + r * SROW + t * 24);
#pragma unroll
        for (int v = 0; v < 6; v++) {
            float4 q4;
            q4.x = px[v*4+0]; q4.y = px[v*4+1]; q4.z = px[v*4+2]; q4.w = px[v*4+3];
            sp[v] = q4;
        }
    }
    __syncthreads();

    // ---- 4. cooperative coalesced store: stage -> y_out ----
    float* ybase = y_out + ((size_t)(b * 512 + bh * 8) * 512 + bw0 * 8) * 3;
#pragma unroll
    for (int i = 0; i < 6; i++) {
        int idx4 = tid + i * 256;
        int row  = idx4 / 192;
        int c4   = idx4 - row * 192;
        float4 v = *(const float4*)(stage + row * SROW + c4 * 4);
        *(float4*)(ybase + row * 1536 + c4 * 4) = v;
    }
}

extern "C" void kernel_launch(void* const* d_in, const int* in_sizes, int n_in,
                              void* d_out, int out_size)
{
    const float* x  = (const float*)d_in[0];
    const float* ql = (const float*)d_in[1];
    const float* qc = (const float*)d_in[2];

    float* y  = (float*)d_out;
    float* xq = (float*)d_out + (size_t)32 * 512 * 512 * 3;

    jpeg_kernel<<<4096, 256>>>(x, ql, qc, y, xq);
}